// round 14
// baseline (speedup 1.0000x reference)
#include <cuda_runtime.h>
#include <math.h>
#include <stdint.h>

#define Bq 64
#define Tq 512
#define Hq 1024
#define G4 4096
#define MTOT (Bq*Tq)
#define NCTA 128

#define WB_F    32768               // resident W: 8192 float4 (128 KB)
#define CHUNK_F 8192                // 64x128 floats per chunk (32 KB)
#define NB      3                   // h buffer ring depth
#define LSTM_SMEM ((WB_F + NB*CHUNK_F)*4)
#define REDS 2176                   // per-wk partial slice (64*34)

__device__ float g_enc_xproj[(size_t)MTOT*G4];
__device__ float g_dec_xproj[(size_t)MTOT*G4];
__device__ float g_dec_hs[(size_t)MTOT*Hq];
__device__ float g_h[2*Bq*Hq];      // [2][8 chunks][64][128], XOR-swizzled
__device__ float g_mlp1[(size_t)MTOT*256];
__device__ float g_mlp2[(size_t)MTOT*128];
__device__ float g_Wt_enc[(size_t)G4*Hq];
__device__ float g_Wt_dec[(size_t)G4*Hq];
__device__ unsigned g_wr[8*32];     // per-chunk producer counters (128B stride)
__device__ unsigned g_rd[8*32];     // per-chunk consumer counters

__device__ __forceinline__ float tf32r(float x){
    uint32_t u; asm("cvt.rna.tf32.f32 %0, %1;" : "=r"(u) : "f"(x));
    return __uint_as_float(u);
}
__device__ __forceinline__ uint32_t fu(float x){ return __float_as_uint(x); }
__device__ __forceinline__ void mma_tf32(float c[4],
    uint32_t a0,uint32_t a1,uint32_t a2,uint32_t a3,uint32_t b0,uint32_t b1){
    asm volatile("mma.sync.aligned.m16n8k8.row.col.f32.tf32.tf32.f32 "
        "{%0,%1,%2,%3}, {%4,%5,%6,%7}, {%8,%9}, {%0,%1,%2,%3};"
        : "+f"(c[0]),"+f"(c[1]),"+f"(c[2]),"+f"(c[3])
        : "r"(a0),"r"(a1),"r"(a2),"r"(a3),"r"(b0),"r"(b1));
}
__device__ __forceinline__ float sigm(float x){ return 1.f/(1.f+expf(-x)); }
__device__ __forceinline__ uint32_t sm2u(const void* p){
    uint32_t a; asm("{ .reg .u64 t; cvta.to.shared.u64 t, %1; cvt.u32.u64 %0, t; }":"=r"(a):"l"(p));
    return a;
}
__device__ __forceinline__ void mbar_init(uint32_t m,uint32_t c){
    asm volatile("mbarrier.init.shared.b64 [%0], %1;"::"r"(m),"r"(c):"memory");
}
__device__ __forceinline__ void mbar_tx(uint32_t m,uint32_t b){
    asm volatile("mbarrier.arrive.expect_tx.shared.b64 _, [%0], %1;"::"r"(m),"r"(b):"memory");
}
__device__ __forceinline__ void mbar_wait(uint32_t m,uint32_t ph){
    asm volatile("{\n\t.reg .pred P;\n\tW%=:\n\t"
        "mbarrier.try_wait.parity.acquire.cta.shared::cta.b64 P, [%0], %1, 0x989680;\n\t"
        "@P bra D%=;\n\tbra W%=;\n\tD%=:\n\t}"::"r"(m),"r"(ph):"memory");
}
__device__ __forceinline__ void fence_async(){
    asm volatile("fence.proxy.async.shared::cta;":::"memory");
}
__device__ __forceinline__ void bulk_g2s(uint32_t d,const float* s,uint32_t b,uint32_t m){
    asm volatile("cp.async.bulk.shared::cta.global.mbarrier::complete_tx::bytes [%0], [%1], %2, [%3];"
        ::"r"(d),"l"(s),"r"(b),"r"(m):"memory");
}
__device__ __forceinline__ void poll_ge(volatile unsigned* p, unsigned tgt){
    while (*p < tgt) { }
}

__global__ void zero_hc_kernel(){
    int i = blockIdx.x*blockDim.x + threadIdx.x;
    if (i < Bq*Hq) g_h[i] = 0.f;
    if (i < 8*32){ g_wr[i] = 0u; g_rd[i] = 0u; }
}

// fragment-packed W (layout verified R5-R13)
__global__ __launch_bounds__(256)
void prep_w_kernel(const float* __restrict__ WE, const float* __restrict__ WD,
                   float4* __restrict__ TE, float4* __restrict__ TD){
    const int half = (blockIdx.x >= 4096);
    const float* Whh = half ? WD : WE;
    float4* Wt4 = half ? TD : TE;
    int idx = (blockIdx.x & 4095)*256 + threadIdx.x;
    int lane = idx & 31;
    int p = (idx >> 5) & 1;
    int gks = (idx >> 6) & 127;
    int cta = idx >> 13;
    int g = lane >> 2, tq = lane & 3;
    int k0 = gks*8 + tq, k1 = k0 + 4;
    int c0 = p*16 + g, c1 = c0 + 8;
    size_t r0 = (size_t)((c0>>3)*Hq + cta*8 + (c0&7))*Hq;
    size_t r1 = (size_t)((c1>>3)*Hq + cta*8 + (c1&7))*Hq;
    float4 v;
    v.x = tf32r(Whh[r0+k0]); v.y = tf32r(Whh[r0+k1]);
    v.z = tf32r(Whh[r1+k0]); v.w = tf32r(Whh[r1+k1]);
    Wt4[idx] = v;
}

__global__ __launch_bounds__(256, 2)
void gemm_tf32_kernel(const float* __restrict__ A, const float* __restrict__ W,
                      const float* __restrict__ b1p, const float* __restrict__ b2p,
                      float* __restrict__ C, int M, int N, int K, int relu){
    __shared__ float As[32][132];
    __shared__ float Bs[32][132];
    const int tid = threadIdx.x, lane = tid&31, wid = tid>>5;
    const int g = lane>>2, tq = lane&3;
    const int wm = wid>>1, wn = wid&1;
    const int bm = blockIdx.y*128, bn = blockIdx.x*128;
    const int kq = tid&7, lr = tid>>3;
    float acc[2][8][4] = {};
    float4 pa[4], pb[4];
#pragma unroll
    for (int p = 0; p < 4; p++){
        pa[p] = *(const float4*)&A[(size_t)(bm+lr+p*32)*K + kq*4];
        pb[p] = *(const float4*)&W[(size_t)(bn+lr+p*32)*K + kq*4];
    }
#pragma unroll
    for (int p = 0; p < 4; p++){
        int m = lr + p*32;
        As[kq*4+0][m]=tf32r(pa[p].x); As[kq*4+1][m]=tf32r(pa[p].y);
        As[kq*4+2][m]=tf32r(pa[p].z); As[kq*4+3][m]=tf32r(pa[p].w);
        Bs[kq*4+0][m]=tf32r(pb[p].x); Bs[kq*4+1][m]=tf32r(pb[p].y);
        Bs[kq*4+2][m]=tf32r(pb[p].z); Bs[kq*4+3][m]=tf32r(pb[p].w);
    }
    __syncthreads();
    const int NK = K/32;
    for (int kt = 0; kt < NK; kt++){
        if (kt+1 < NK){
            int k0 = (kt+1)*32;
#pragma unroll
            for (int p = 0; p < 4; p++){
                pa[p] = *(const float4*)&A[(size_t)(bm+lr+p*32)*K + k0 + kq*4];
                pb[p] = *(const float4*)&W[(size_t)(bn+lr+p*32)*K + k0 + kq*4];
            }
        }
#pragma unroll
        for (int ks = 0; ks < 4; ks++){
            const int kb = ks*8;
            uint32_t a[2][4], b[8][2];
#pragma unroll
            for (int mf = 0; mf < 2; mf++){
                int r = wm*32 + mf*16 + g;
                a[mf][0]=fu(As[kb+tq][r]);   a[mf][1]=fu(As[kb+tq][r+8]);
                a[mf][2]=fu(As[kb+tq+4][r]); a[mf][3]=fu(As[kb+tq+4][r+8]);
            }
#pragma unroll
            for (int nf = 0; nf < 8; nf++){
                int cn = wn*64 + nf*8 + g;
                b[nf][0]=fu(Bs[kb+tq][cn]); b[nf][1]=fu(Bs[kb+tq+4][cn]);
            }
#pragma unroll
            for (int mf = 0; mf < 2; mf++)
#pragma unroll
                for (int nf = 0; nf < 8; nf++)
                    mma_tf32(acc[mf][nf], a[mf][0],a[mf][1],a[mf][2],a[mf][3],
                             b[nf][0],b[nf][1]);
        }
        __syncthreads();
        if (kt+1 < NK){
#pragma unroll
            for (int p = 0; p < 4; p++){
                int m = lr + p*32;
                As[kq*4+0][m]=tf32r(pa[p].x); As[kq*4+1][m]=tf32r(pa[p].y);
                As[kq*4+2][m]=tf32r(pa[p].z); As[kq*4+3][m]=tf32r(pa[p].w);
                Bs[kq*4+0][m]=tf32r(pb[p].x); Bs[kq*4+1][m]=tf32r(pb[p].y);
                Bs[kq*4+2][m]=tf32r(pb[p].z); Bs[kq*4+3][m]=tf32r(pb[p].w);
            }
            __syncthreads();
        }
    }
#pragma unroll
    for (int mf = 0; mf < 2; mf++){
        int row = bm + wm*32 + mf*16 + g;
#pragma unroll
        for (int nf = 0; nf < 8; nf++){
            int col = bn + wn*64 + nf*8 + 2*tq;
            float c0 = 0.f, c1 = 0.f;
            if (b1p){ c0 = b1p[col]; c1 = b1p[col+1]; }
            if (b2p){ c0 += b2p[col]; c1 += b2p[col+1]; }
            float v0 = acc[mf][nf][0]+c0, v1 = acc[mf][nf][1]+c1;
            float v2 = acc[mf][nf][2]+c0, v3 = acc[mf][nf][3]+c1;
            if (relu){ v0=fmaxf(v0,0.f); v1=fmaxf(v1,0.f); v2=fmaxf(v2,0.f); v3=fmaxf(v3,0.f); }
            float2 lo = {v0,v1}, hi = {v2,v3};
            *(float2*)&C[(size_t)row*N + col] = lo;
            *(float2*)&C[(size_t)(row+8)*N + col] = hi;
        }
    }
}

// persistent LSTM: fine-grained per-chunk dataflow, NO global barrier
__global__ __launch_bounds__(512, 1)
void lstm_persistent_kernel(const float* __restrict__ enc_xp,
                            const float* __restrict__ dec_xp,
                            float* __restrict__ dec_hs){
    extern __shared__ float smem[];
    float4* Wb4 = (float4*)smem;
    float*  HsA = smem + WB_F;
    float*  Red = HsA;                  // aliases ring buf0 (free when reduce runs)
    __shared__ __align__(8) unsigned long long mbars[NB];

    const uint32_t buf0 = sm2u(smem) + WB_F*4;
    const int tid = threadIdx.x, lane = tid&31, wid = tid>>5;
    const int g = lane>>2, tq = lane&3;
    const int wk = wid>>3, wm = (wid>>1)&3, wn = wid&1;
    const int r0 = wm*16 + g;
    const int gx = g<<2;
    const int j0 = blockIdx.x*8;
    const int own = blockIdx.x >> 4;     // chunk this CTA's cols belong to
    const int pm = tid>>3, pj = tid&7;
    const int pcol = j0 + pj;
    const int pchunk = pcol>>7;
    const int psw = (pcol & 127) ^ ((pm&7)<<2);
    const int pdst = pchunk*CHUNK_F + pm*128 + psw;

    const float4* WtE = (const float4*)g_Wt_enc + (size_t)blockIdx.x*8192;
    const float4* WtD = (const float4*)g_Wt_dec + (size_t)blockIdx.x*8192;

    if (tid == 0){
#pragma unroll
        for (int i = 0; i < NB; i++) mbar_init(sm2u(&mbars[i]), 1);
    }
    __syncthreads();
    int ph[NB] = {0, 0, 0};
    float creg = 0.f;

    for (int s = 0; s < 2*Tq; s++){
        const int enc = (s < Tq);
        const int t = enc ? s : (s - Tq);
        const float* __restrict__ xproj = enc ? enc_xp : dec_xp;
        const float* __restrict__ h_in = g_h + (s&1)*(Bq*Hq);
        float* __restrict__ h_out = g_h + ((s+1)&1)*(Bq*Hq);
        const unsigned wrt = 16u * (unsigned)s;   // producer-count target

        if (s == 0 || s == Tq){
            const float4* src = enc ? WtE : WtD;
#pragma unroll
            for (int j = 0; j < 16; j++) Wb4[j*512 + tid] = src[j*512 + tid];
            __syncthreads();
        }

        // issue first NB chunks (rotated: own chunk first), gated on producers
        if (tid == 0){
            fence_async();
#pragma unroll
            for (int b = 0; b < NB; b++){
                int cc = (own + b) & 7;
                poll_ge(&g_wr[cc*32], wrt);
                mbar_tx(sm2u(&mbars[b]), CHUNK_F*4);
                bulk_g2s(buf0 + b*CHUNK_F*4, h_in + cc*CHUNK_F, CHUNK_F*4, sm2u(&mbars[b]));
            }
        }

        float xg0, xg1, xg2, xg3;
        {
            size_t xb = ((size_t)pm*Tq + t)*G4 + pcol;
            xg0 = xproj[xb];        xg1 = xproj[xb + Hq];
            xg2 = xproj[xb + 2*Hq]; xg3 = xproj[xb + 3*Hq];
        }

        float acc[2][4] = {};

        for (int kt = 0; kt < 8; kt++){
            const int b = kt % NB;
            const int cc = (own + kt) & 7;
            mbar_wait(sm2u(&mbars[b]), (unsigned)ph[b]); ph[b] ^= 1;
            if (tid == 0) atomicAdd(&g_rd[cc*32], 1u);   // global buffer slice free

            const float* Hs = HsA + b*CHUNK_F;
#pragma unroll
            for (int ks = 0; ks < 8; ks++){
                const int kl = wk*8 + ks;
                const int kb = kl*8;
                float4 wv = Wb4[(((cc*16 + kl)*2) + wn)*32 + lane];
                const int c0 = (kb + tq) ^ gx;
                const int c1 = (kb + tq + 4) ^ gx;
                uint32_t a0 = fu(Hs[r0*128 + c0]);
                uint32_t a1 = fu(Hs[(r0+8)*128 + c0]);
                uint32_t a2 = fu(Hs[r0*128 + c1]);
                uint32_t a3 = fu(Hs[(r0+8)*128 + c1]);
                mma_tf32(acc[0], a0, a1, a2, a3, fu(wv.x), fu(wv.y));
                mma_tf32(acc[1], a0, a1, a2, a3, fu(wv.z), fu(wv.w));
            }
            __syncthreads();                 // ring buffer b free

            if (kt < 5 && tid == 0){
                int cc2 = (own + kt + 3) & 7;
                poll_ge(&g_wr[cc2*32], wrt);
                fence_async();
                mbar_tx(sm2u(&mbars[b]), CHUNK_F*4);
                bulk_g2s(buf0 + b*CHUNK_F*4, h_in + cc2*CHUNK_F, CHUNK_F*4,
                         sm2u(&mbars[b]));
            }
        }

        // per-wk partials (stride 34)
        {
            float* Rw = Red + wk*REDS;
            int cb = wn*16;
#pragma unroll
            for (int nt = 0; nt < 2; nt++){
                int col = cb + nt*8 + 2*tq;
                float2 lo = {acc[nt][0], acc[nt][1]};
                float2 hi = {acc[nt][2], acc[nt][3]};
                *(float2*)&Rw[r0*34 + col]     = lo;
                *(float2*)&Rw[(r0+8)*34 + col] = hi;
            }
        }
        __syncthreads();

        // fused reduce + pointwise
        float hn;
        {
            const float* c0p = &Red[pm*34 + pj];
            const float* c1p = &Red[REDS + pm*34 + pj];
            float ig = c0p[0]  + c1p[0]  + xg0;
            float fg = c0p[8]  + c1p[8]  + xg1;
            float gg = c0p[16] + c1p[16] + xg2;
            float og = c0p[24] + c1p[24] + xg3;
            float cn = sigm(fg)*creg + sigm(ig)*tanhf(gg);
            creg = cn;
            hn = tf32r(sigm(og)*tanhf(cn));
        }

        // WAR: step s-1 readers of h_out's buffer slice must be done
        if (tid == 0) poll_ge(&g_rd[own*32], 128u*(unsigned)s);
        __syncthreads();

        h_out[pdst] = hn;
        if (!enc) dec_hs[((size_t)pm*Tq + t)*Hq + pcol] = hn;
        __syncthreads();
        if (tid == 0){
            __threadfence();
            atomicAdd(&g_wr[own*32], 1u);    // publish this CTA's 8 cols
        }
    }
}

extern "C" void kernel_launch(void* const* d_in, const int* in_sizes, int n_in,
                              void* d_out, int out_size){
    const float* input_seq  = (const float*)d_in[0];
    const float* target_seq = (const float*)d_in[1];
    const float* enc_Wih = (const float*)d_in[2];
    const float* enc_Whh = (const float*)d_in[3];
    const float* enc_bih = (const float*)d_in[4];
    const float* enc_bhh = (const float*)d_in[5];
    const float* dec_Wih = (const float*)d_in[6];
    const float* dec_Whh = (const float*)d_in[7];
    const float* dec_bih = (const float*)d_in[8];
    const float* dec_bhh = (const float*)d_in[9];
    const float* W1 = (const float*)d_in[10];
    const float* b1 = (const float*)d_in[11];
    const float* W2 = (const float*)d_in[12];
    const float* b2 = (const float*)d_in[13];
    const float* W3 = (const float*)d_in[14];
    const float* b3 = (const float*)d_in[15];
    float* out = (float*)d_out;

    float *enc_xp, *dec_xp, *dec_hs, *m1, *m2, *wte, *wtd;
    cudaGetSymbolAddress((void**)&enc_xp, g_enc_xproj);
    cudaGetSymbolAddress((void**)&dec_xp, g_dec_xproj);
    cudaGetSymbolAddress((void**)&dec_hs, g_dec_hs);
    cudaGetSymbolAddress((void**)&m1, g_mlp1);
    cudaGetSymbolAddress((void**)&m2, g_mlp2);
    cudaGetSymbolAddress((void**)&wte, g_Wt_enc);
    cudaGetSymbolAddress((void**)&wtd, g_Wt_dec);

    static int once = 0;
    if (!once){
        cudaFuncSetAttribute(lstm_persistent_kernel,
                             cudaFuncAttributeMaxDynamicSharedMemorySize, LSTM_SMEM);
        once = 1;
    }

    zero_hc_kernel<<<(Bq*Hq + 255)/256, 256>>>();
    prep_w_kernel<<<8192, 256>>>(enc_Whh, dec_Whh, (float4*)wte, (float4*)wtd);

    gemm_tf32_kernel<<<dim3(G4/128, MTOT/128), 256>>>(
        input_seq, enc_Wih, enc_bih, enc_bhh, enc_xp, MTOT, G4, 256, 0);
    gemm_tf32_kernel<<<dim3(G4/128, MTOT/128), 256>>>(
        target_seq, dec_Wih, dec_bih, dec_bhh, dec_xp, MTOT, G4, Hq, 0);

    lstm_persistent_kernel<<<NCTA, 512, LSTM_SMEM>>>(enc_xp, dec_xp, dec_hs);

    gemm_tf32_kernel<<<dim3(256/128, MTOT/128), 256>>>(
        dec_hs, W1, b1, nullptr, m1, MTOT, 256, Hq, 1);
    gemm_tf32_kernel<<<dim3(128/128, MTOT/128), 256>>>(
        m1, W2, b2, nullptr, m2, MTOT, 128, 256, 1);
    gemm_tf32_kernel<<<dim3(256/128, MTOT/128), 256>>>(
        m2, W3, b3, nullptr, out, MTOT, 256, 128, 0);
}

// round 15
// speedup vs baseline: 1.1501x; 1.1501x over previous
#include <cuda_runtime.h>
#include <math.h>
#include <stdint.h>

#define Bq 64
#define Tq 512
#define Hq 1024
#define G4 4096
#define MTOT (Bq*Tq)
#define NCTA 128

#define WB_F    32768               // resident W: 8192 float4 (128 KB)
#define CHUNK_F 8192                // 64x128 floats per chunk (32 KB)
#define NB      3                   // h buffer ring depth
#define LSTM_SMEM ((WB_F + NB*CHUNK_F)*4)
#define REDS 2176                   // per-wk partial slice (64*34 floats)

__device__ float g_enc_xproj[(size_t)MTOT*G4];
__device__ float g_dec_xproj[(size_t)MTOT*G4];
__device__ float g_dec_hs[(size_t)MTOT*Hq];
__device__ float g_h[2*Bq*Hq];      // [2][8 chunks][64][128], XOR-swizzled
__device__ float g_mlp1[(size_t)MTOT*256];
__device__ float g_mlp2[(size_t)MTOT*128];
__device__ float g_Wt_enc[(size_t)G4*Hq];
__device__ float g_Wt_dec[(size_t)G4*Hq];
__device__ unsigned g_bar;

__device__ __forceinline__ float tf32r(float x){
    uint32_t u; asm("cvt.rna.tf32.f32 %0, %1;" : "=r"(u) : "f"(x));
    return __uint_as_float(u);
}
__device__ __forceinline__ uint32_t fu(float x){ return __float_as_uint(x); }
__device__ __forceinline__ void mma_tf32(float c[4],
    uint32_t a0,uint32_t a1,uint32_t a2,uint32_t a3,uint32_t b0,uint32_t b1){
    asm volatile("mma.sync.aligned.m16n8k8.row.col.f32.tf32.tf32.f32 "
        "{%0,%1,%2,%3}, {%4,%5,%6,%7}, {%8,%9}, {%0,%1,%2,%3};"
        : "+f"(c[0]),"+f"(c[1]),"+f"(c[2]),"+f"(c[3])
        : "r"(a0),"r"(a1),"r"(a2),"r"(a3),"r"(b0),"r"(b1));
}
__device__ __forceinline__ float sigm(float x){ return 1.f/(1.f+expf(-x)); }
__device__ __forceinline__ uint32_t sm2u(const void* p){
    uint32_t a; asm("{ .reg .u64 t; cvta.to.shared.u64 t, %1; cvt.u32.u64 %0, t; }":"=r"(a):"l"(p));
    return a;
}
__device__ __forceinline__ void mbar_init(uint32_t m,uint32_t c){
    asm volatile("mbarrier.init.shared.b64 [%0], %1;"::"r"(m),"r"(c):"memory");
}
__device__ __forceinline__ void mbar_tx(uint32_t m,uint32_t b){
    asm volatile("mbarrier.arrive.expect_tx.shared.b64 _, [%0], %1;"::"r"(m),"r"(b):"memory");
}
__device__ __forceinline__ void mbar_wait(uint32_t m,uint32_t ph){
    asm volatile("{\n\t.reg .pred P;\n\tW%=:\n\t"
        "mbarrier.try_wait.parity.acquire.cta.shared::cta.b64 P, [%0], %1, 0x989680;\n\t"
        "@P bra D%=;\n\tbra W%=;\n\tD%=:\n\t}"::"r"(m),"r"(ph):"memory");
}
__device__ __forceinline__ void fence_async(){
    asm volatile("fence.proxy.async.shared::cta;":::"memory");
}
__device__ __forceinline__ void bulk_g2s(uint32_t d,const float* s,uint32_t b,uint32_t m){
    asm volatile("cp.async.bulk.shared::cta.global.mbarrier::complete_tx::bytes [%0], [%1], %2, [%3];"
        ::"r"(d),"l"(s),"r"(b),"r"(m):"memory");
}

__global__ void zero_hc_kernel(){
    int i = blockIdx.x*blockDim.x + threadIdx.x;
    if (i < Bq*Hq) g_h[i] = 0.f;
    if (i == 0) g_bar = 0u;
}

// fragment-packed W (layout verified R5-R13)
__global__ __launch_bounds__(256)
void prep_w_kernel(const float* __restrict__ WE, const float* __restrict__ WD,
                   float4* __restrict__ TE, float4* __restrict__ TD){
    const int half = (blockIdx.x >= 4096);
    const float* Whh = half ? WD : WE;
    float4* Wt4 = half ? TD : TE;
    int idx = (blockIdx.x & 4095)*256 + threadIdx.x;
    int lane = idx & 31;
    int p = (idx >> 5) & 1;
    int gks = (idx >> 6) & 127;
    int cta = idx >> 13;
    int g = lane >> 2, tq = lane & 3;
    int k0 = gks*8 + tq, k1 = k0 + 4;
    int c0 = p*16 + g, c1 = c0 + 8;
    size_t r0 = (size_t)((c0>>3)*Hq + cta*8 + (c0&7))*Hq;
    size_t r1 = (size_t)((c1>>3)*Hq + cta*8 + (c1&7))*Hq;
    float4 v;
    v.x = tf32r(Whh[r0+k0]); v.y = tf32r(Whh[r0+k1]);
    v.z = tf32r(Whh[r1+k0]); v.w = tf32r(Whh[r1+k1]);
    Wt4[idx] = v;
}

__global__ __launch_bounds__(256, 2)
void gemm_tf32_kernel(const float* __restrict__ A, const float* __restrict__ W,
                      const float* __restrict__ b1p, const float* __restrict__ b2p,
                      float* __restrict__ C, int M, int N, int K, int relu){
    __shared__ float As[32][132];
    __shared__ float Bs[32][132];
    const int tid = threadIdx.x, lane = tid&31, wid = tid>>5;
    const int g = lane>>2, tq = lane&3;
    const int wm = wid>>1, wn = wid&1;
    const int bm = blockIdx.y*128, bn = blockIdx.x*128;
    const int kq = tid&7, lr = tid>>3;
    float acc[2][8][4] = {};
    float4 pa[4], pb[4];
#pragma unroll
    for (int p = 0; p < 4; p++){
        pa[p] = *(const float4*)&A[(size_t)(bm+lr+p*32)*K + kq*4];
        pb[p] = *(const float4*)&W[(size_t)(bn+lr+p*32)*K + kq*4];
    }
#pragma unroll
    for (int p = 0; p < 4; p++){
        int m = lr + p*32;
        As[kq*4+0][m]=tf32r(pa[p].x); As[kq*4+1][m]=tf32r(pa[p].y);
        As[kq*4+2][m]=tf32r(pa[p].z); As[kq*4+3][m]=tf32r(pa[p].w);
        Bs[kq*4+0][m]=tf32r(pb[p].x); Bs[kq*4+1][m]=tf32r(pb[p].y);
        Bs[kq*4+2][m]=tf32r(pb[p].z); Bs[kq*4+3][m]=tf32r(pb[p].w);
    }
    __syncthreads();
    const int NK = K/32;
    for (int kt = 0; kt < NK; kt++){
        if (kt+1 < NK){
            int k0 = (kt+1)*32;
#pragma unroll
            for (int p = 0; p < 4; p++){
                pa[p] = *(const float4*)&A[(size_t)(bm+lr+p*32)*K + k0 + kq*4];
                pb[p] = *(const float4*)&W[(size_t)(bn+lr+p*32)*K + k0 + kq*4];
            }
        }
#pragma unroll
        for (int ks = 0; ks < 4; ks++){
            const int kb = ks*8;
            uint32_t a[2][4], b[8][2];
#pragma unroll
            for (int mf = 0; mf < 2; mf++){
                int r = wm*32 + mf*16 + g;
                a[mf][0]=fu(As[kb+tq][r]);   a[mf][1]=fu(As[kb+tq][r+8]);
                a[mf][2]=fu(As[kb+tq+4][r]); a[mf][3]=fu(As[kb+tq+4][r+8]);
            }
#pragma unroll
            for (int nf = 0; nf < 8; nf++){
                int cn = wn*64 + nf*8 + g;
                b[nf][0]=fu(Bs[kb+tq][cn]); b[nf][1]=fu(Bs[kb+tq+4][cn]);
            }
#pragma unroll
            for (int mf = 0; mf < 2; mf++)
#pragma unroll
                for (int nf = 0; nf < 8; nf++)
                    mma_tf32(acc[mf][nf], a[mf][0],a[mf][1],a[mf][2],a[mf][3],
                             b[nf][0],b[nf][1]);
        }
        __syncthreads();
        if (kt+1 < NK){
#pragma unroll
            for (int p = 0; p < 4; p++){
                int m = lr + p*32;
                As[kq*4+0][m]=tf32r(pa[p].x); As[kq*4+1][m]=tf32r(pa[p].y);
                As[kq*4+2][m]=tf32r(pa[p].z); As[kq*4+3][m]=tf32r(pa[p].w);
                Bs[kq*4+0][m]=tf32r(pb[p].x); Bs[kq*4+1][m]=tf32r(pb[p].y);
                Bs[kq*4+2][m]=tf32r(pb[p].z); Bs[kq*4+3][m]=tf32r(pb[p].w);
            }
            __syncthreads();
        }
    }
#pragma unroll
    for (int mf = 0; mf < 2; mf++){
        int row = bm + wm*32 + mf*16 + g;
#pragma unroll
        for (int nf = 0; nf < 8; nf++){
            int col = bn + wn*64 + nf*8 + 2*tq;
            float c0 = 0.f, c1 = 0.f;
            if (b1p){ c0 = b1p[col]; c1 = b1p[col+1]; }
            if (b2p){ c0 += b2p[col]; c1 += b2p[col+1]; }
            float v0 = acc[mf][nf][0]+c0, v1 = acc[mf][nf][1]+c1;
            float v2 = acc[mf][nf][2]+c0, v3 = acc[mf][nf][3]+c1;
            if (relu){ v0=fmaxf(v0,0.f); v1=fmaxf(v1,0.f); v2=fmaxf(v2,0.f); v3=fmaxf(v3,0.f); }
            float2 lo = {v0,v1}, hi = {v2,v3};
            *(float2*)&C[(size_t)row*N + col] = lo;
            *(float2*)&C[(size_t)(row+8)*N + col] = hi;
        }
    }
}

__device__ __forceinline__ void grid_bar(unsigned target){
    __syncthreads();
    if (threadIdx.x == 0){
        __threadfence();
        atomicAdd(&g_bar, 1u);
        volatile unsigned* p = &g_bar;
        while (*p < target) { }
        __threadfence();
    }
    __syncthreads();
}

// persistent LSTM: wk8 x wm2 x wn1 warp layout (min crossbar duplication)
__global__ __launch_bounds__(512, 1)
void lstm_persistent_kernel(const float* __restrict__ enc_xp,
                            const float* __restrict__ dec_xp,
                            float* __restrict__ dec_hs){
    extern __shared__ float smem[];
    float4* Wb4 = (float4*)smem;
    float*  HsA = smem + WB_F;
    float*  Red = HsA;                  // 8 partial slices alias ring (69.6 KB < 96 KB)
    __shared__ __align__(8) unsigned long long mbars[NB];

    const uint32_t buf0 = sm2u(smem) + WB_F*4;
    const int tid = threadIdx.x, lane = tid&31, wid = tid>>5;
    const int g = lane>>2, tq = lane&3;
    const int wk = wid >> 1;             // k-group 0..7 (owns kl = wk*2, wk*2+1)
    const int wm = wid & 1;              // m-group 0..1 (rows wm*32 .. +31)
    const int gx = g<<2;
    const int j0 = blockIdx.x*8;
    const int pm = tid>>3, pj = tid&7;
    const int pcol = j0 + pj;
    const int pchunk = pcol>>7;
    const int psw = (pcol & 127) ^ ((pm&7)<<2);
    const int pdst = pchunk*CHUNK_F + pm*128 + psw;

    const float4* WtE = (const float4*)g_Wt_enc + (size_t)blockIdx.x*8192;
    const float4* WtD = (const float4*)g_Wt_dec + (size_t)blockIdx.x*8192;

    if (tid == 0){
#pragma unroll
        for (int i = 0; i < NB; i++) mbar_init(sm2u(&mbars[i]), 1);
    }
    __syncthreads();
    int ph[NB] = {0, 0, 0};
    float creg = 0.f;

    for (int s = 0; s < 2*Tq; s++){
        const int enc = (s < Tq);
        const int t = enc ? s : (s - Tq);
        const float* __restrict__ xproj = enc ? enc_xp : dec_xp;
        const float* __restrict__ h_in = g_h + (s&1)*(Bq*Hq);
        float* __restrict__ h_out = g_h + ((s+1)&1)*(Bq*Hq);

        if (s == 0 || s == Tq){
            const float4* src = enc ? WtE : WtD;
#pragma unroll
            for (int j = 0; j < 16; j++) Wb4[j*512 + tid] = src[j*512 + tid];
            __syncthreads();
        }

        if (tid == 0){
            fence_async();
#pragma unroll
            for (int b = 0; b < NB; b++){
                mbar_tx(sm2u(&mbars[b]), CHUNK_F*4);
                bulk_g2s(buf0 + b*CHUNK_F*4, h_in + b*CHUNK_F, CHUNK_F*4, sm2u(&mbars[b]));
            }
        }

        float xg0, xg1, xg2, xg3;
        {
            size_t xb = ((size_t)pm*Tq + t)*G4 + pcol;
            xg0 = xproj[xb];        xg1 = xproj[xb + Hq];
            xg2 = xproj[xb + 2*Hq]; xg3 = xproj[xb + 3*Hq];
        }

        float acc[2][4][4] = {};      // [mf][nf][4] = m32 x n32, k-split 1/8

        for (int kt = 0; kt < 8; kt++){
            const int b = kt % NB;
            mbar_wait(sm2u(&mbars[b]), (unsigned)ph[b]); ph[b] ^= 1;

            const float* Hs = HsA + b*CHUNK_F;
#pragma unroll
            for (int j = 0; j < 2; j++){
                const int kl = wk*2 + j;
                const int kb = kl*8;
                float4 f0 = Wb4[(((kt*16 + kl)*2) + 0)*32 + lane];
                float4 f1 = Wb4[(((kt*16 + kl)*2) + 1)*32 + lane];
                const int c0 = (kb + tq) ^ gx;
                const int c1 = (kb + tq + 4) ^ gx;
#pragma unroll
                for (int mf = 0; mf < 2; mf++){
                    const int r = wm*32 + mf*16 + g;
                    uint32_t a0 = fu(Hs[r*128 + c0]);
                    uint32_t a1 = fu(Hs[(r+8)*128 + c0]);
                    uint32_t a2 = fu(Hs[r*128 + c1]);
                    uint32_t a3 = fu(Hs[(r+8)*128 + c1]);
                    mma_tf32(acc[mf][0], a0, a1, a2, a3, fu(f0.x), fu(f0.y));
                    mma_tf32(acc[mf][1], a0, a1, a2, a3, fu(f0.z), fu(f0.w));
                    mma_tf32(acc[mf][2], a0, a1, a2, a3, fu(f1.x), fu(f1.y));
                    mma_tf32(acc[mf][3], a0, a1, a2, a3, fu(f1.z), fu(f1.w));
                }
            }
            __syncthreads();                 // ring buffer b free

            if (kt < 5 && tid == 0){
                fence_async();
                mbar_tx(sm2u(&mbars[b]), CHUNK_F*4);
                bulk_g2s(buf0 + b*CHUNK_F*4, h_in + (kt+3)*CHUNK_F, CHUNK_F*4,
                         sm2u(&mbars[b]));
            }
        }

        // per-wk partials: slice wk holds rows 0..63 x cols 0..31 (stride 34)
        {
            float* Rw = Red + wk*REDS;
#pragma unroll
            for (int mf = 0; mf < 2; mf++){
                int rr = wm*32 + mf*16 + g;
#pragma unroll
                for (int nf = 0; nf < 4; nf++){
                    int col = nf*8 + 2*tq;
                    float2 lo = {acc[mf][nf][0], acc[mf][nf][1]};
                    float2 hi = {acc[mf][nf][2], acc[mf][nf][3]};
                    *(float2*)&Rw[rr*34 + col]     = lo;
                    *(float2*)&Rw[(rr+8)*34 + col] = hi;
                }
            }
        }
        __syncthreads();

        // fused 8-way reduce + pointwise (1 col/thread)
        {
            float sg0 = 0.f, sg1 = 0.f, sg2 = 0.f, sg3 = 0.f;
#pragma unroll
            for (int p = 0; p < 8; p++){
                const float* rp = &Red[p*REDS + pm*34 + pj];
                sg0 += rp[0]; sg1 += rp[8]; sg2 += rp[16]; sg3 += rp[24];
            }
            float ig = sg0 + xg0, fg = sg1 + xg1, gg = sg2 + xg2, og = sg3 + xg3;
            float cn = sigm(fg)*creg + sigm(ig)*tanhf(gg);
            creg = cn;
            float hn = tf32r(sigm(og)*tanhf(cn));
            h_out[pdst] = hn;
            if (!enc) dec_hs[((size_t)pm*Tq + t)*Hq + pcol] = hn;
        }

        grid_bar((unsigned)(s+1)*NCTA);
    }
}

extern "C" void kernel_launch(void* const* d_in, const int* in_sizes, int n_in,
                              void* d_out, int out_size){
    const float* input_seq  = (const float*)d_in[0];
    const float* target_seq = (const float*)d_in[1];
    const float* enc_Wih = (const float*)d_in[2];
    const float* enc_Whh = (const float*)d_in[3];
    const float* enc_bih = (const float*)d_in[4];
    const float* enc_bhh = (const float*)d_in[5];
    const float* dec_Wih = (const float*)d_in[6];
    const float* dec_Whh = (const float*)d_in[7];
    const float* dec_bih = (const float*)d_in[8];
    const float* dec_bhh = (const float*)d_in[9];
    const float* W1 = (const float*)d_in[10];
    const float* b1 = (const float*)d_in[11];
    const float* W2 = (const float*)d_in[12];
    const float* b2 = (const float*)d_in[13];
    const float* W3 = (const float*)d_in[14];
    const float* b3 = (const float*)d_in[15];
    float* out = (float*)d_out;

    float *enc_xp, *dec_xp, *dec_hs, *m1, *m2, *wte, *wtd;
    cudaGetSymbolAddress((void**)&enc_xp, g_enc_xproj);
    cudaGetSymbolAddress((void**)&dec_xp, g_dec_xproj);
    cudaGetSymbolAddress((void**)&dec_hs, g_dec_hs);
    cudaGetSymbolAddress((void**)&m1, g_mlp1);
    cudaGetSymbolAddress((void**)&m2, g_mlp2);
    cudaGetSymbolAddress((void**)&wte, g_Wt_enc);
    cudaGetSymbolAddress((void**)&wtd, g_Wt_dec);

    static int once = 0;
    if (!once){
        cudaFuncSetAttribute(lstm_persistent_kernel,
                             cudaFuncAttributeMaxDynamicSharedMemorySize, LSTM_SMEM);
        once = 1;
    }

    zero_hc_kernel<<<(Bq*Hq + 255)/256, 256>>>();
    prep_w_kernel<<<8192, 256>>>(enc_Whh, dec_Whh, (float4*)wte, (float4*)wtd);

    gemm_tf32_kernel<<<dim3(G4/128, MTOT/128), 256>>>(
        input_seq, enc_Wih, enc_bih, enc_bhh, enc_xp, MTOT, G4, 256, 0);
    gemm_tf32_kernel<<<dim3(G4/128, MTOT/128), 256>>>(
        target_seq, dec_Wih, dec_bih, dec_bhh, dec_xp, MTOT, G4, Hq, 0);

    lstm_persistent_kernel<<<NCTA, 512, LSTM_SMEM>>>(enc_xp, dec_xp, dec_hs);

    gemm_tf32_kernel<<<dim3(256/128, MTOT/128), 256>>>(
        dec_hs, W1, b1, nullptr, m1, MTOT, 256, Hq, 1);
    gemm_tf32_kernel<<<dim3(128/128, MTOT/128), 256>>>(
        m1, W2, b2, nullptr, m2, MTOT, 128, 256, 1);
    gemm_tf32_kernel<<<dim3(256/128, MTOT/128), 256>>>(
        m2, W3, b3, nullptr, out, MTOT, 256, 128, 0);
}